// round 10
// baseline (speedup 1.0000x reference)
#include <cuda_runtime.h>

typedef unsigned long long u64;

// ---------- f32x2 packed helpers (Blackwell sm_103a) ----------
__device__ __forceinline__ u64 pk2(float lo, float hi) {
    u64 r; asm("mov.b64 %0,{%1,%2};" : "=l"(r) : "f"(lo), "f"(hi)); return r;
}
__device__ __forceinline__ void unpk2(u64 v, float& lo, float& hi) {
    asm("mov.b64 {%0,%1},%2;" : "=f"(lo), "=f"(hi) : "l"(v));
}
__device__ __forceinline__ u64 fma2(u64 a, u64 b, u64 c) {
    u64 d; asm("fma.rn.f32x2 %0,%1,%2,%3;" : "=l"(d) : "l"(a), "l"(b), "l"(c)); return d;
}
__device__ __forceinline__ u64 add2(u64 a, u64 b) {
    u64 d; asm("add.rn.f32x2 %0,%1,%2;" : "=l"(d) : "l"(a), "l"(b)); return d;
}
__device__ __forceinline__ u64 mul2(u64 a, u64 b) {
    u64 d; asm("mul.rn.f32x2 %0,%1,%2;" : "=l"(d) : "l"(a), "l"(b)); return d;
}
__device__ __forceinline__ u64 shfl64(u64 v, int m) {
    return __shfl_xor_sync(0xffffffffu, v, m);
}

// ---------- activations ----------
__device__ __forceinline__ float ex2a(float x) {
    float y; asm("ex2.approx.f32 %0,%1;" : "=f"(y) : "f"(x)); return y;
}
__device__ __forceinline__ float rcpa(float x) {
    float y; asm("rcp.approx.f32 %0,%1;" : "=f"(y) : "f"(x)); return y;
}
#define SSC (-1.4426950408889634f)     /* -log2(e)   : sigmoid pre-scale */
#define TSC (-2.8853900817779268f)     /* -2*log2(e) : tanh pre-scale    */
#define INV_TSC (-0.3465735902799726f) /* 1/TSC                          */

__device__ __forceinline__ float sigS(float s)  { return rcpa(1.0f + ex2a(s)); }
__device__ __forceinline__ float tanhU(float s) { return fmaf(2.0f, rcpa(1.0f + ex2a(s)), -1.0f); }

// One warp per batch row; cloc carried PRE-SCALED by TSC on all lanes.
// Lanes 0-19: layer-1 unit j=lane (dots over h-section of smem).
// Lane 20   : all four layer-2 gates (dots over c-section, weights /TSC);
//             its h2-recurrent term rides in the x-operand slot (xl = hloc).
// Fused reciprocals: sig(i)*tanh(g) and sig(o)*tanh(c) take ONE rcp each
// -> 8 MUFU/step. The c-update keeps the TSC scale via ig = TSC*(1-Eg)*igR.
__global__ void __launch_bounds__(128)
lstm_warp_kernel(const float* __restrict__ xin,
                 const float* __restrict__ Wih1, const float* __restrict__ Whh1,
                 const float* __restrict__ bih1, const float* __restrict__ bhh1,
                 const float* __restrict__ Wih2, const float* __restrict__ Whh2,
                 const float* __restrict__ bih2, const float* __restrict__ bhh2,
                 float* __restrict__ out, int B, int T, int F)
{
    const int w    = threadIdx.x >> 5;
    const int lane = threadIdx.x & 31;
    const int b    = blockIdx.x * 4 + w;

    // [warp][ping][0:32)=(h,h) dup, [32:64)=(TSC*c, TSC*c) dup
    __shared__ __align__(16) u64 sbuf[4][2][64];

    if (b >= B) return;

    const bool is20 = (lane == 20);
    const int  sec  = (lane < 20) ? 0 : 32;
    u64* const wb   = &sbuf[w][0][0];

    // ---- per-lane weights (prescaled); default zero ----
    u64 wif[20], wgo[20];
#pragma unroll
    for (int k = 0; k < 20; k++) { wif[k] = 0ull; wgo[k] = 0ull; }
    u64 wxif = 0ull, wxgo = 0ull, bif = 0ull, bgo = 0ull;

    if (lane < 20) {
        const int j = lane;
#pragma unroll
        for (int k = 0; k < 20; k++) {
            wif[k] = pk2(SSC * Whh1[j * 20 + k],        SSC * Whh1[(20 + j) * 20 + k]);
            wgo[k] = pk2(TSC * Whh1[(40 + j) * 20 + k], SSC * Whh1[(60 + j) * 20 + k]);
        }
        wxif = pk2(SSC * Wih1[j],      SSC * Wih1[20 + j]);
        wxgo = pk2(TSC * Wih1[40 + j], SSC * Wih1[60 + j]);
        bif  = pk2(SSC * (bih1[j] + bhh1[j]),
                   SSC * (bih1[20 + j] + bhh1[20 + j]));
        bgo  = pk2(TSC * (bih1[40 + j] + bhh1[40 + j]),
                   SSC * (bih1[60 + j] + bhh1[60 + j]));
    } else if (lane == 20) {
        // L2 dots read TSC*c1 -> fold 1/TSC into the weights.
        // x-operand slot carries h2 (xl = hloc) -> wx := wh2.
#pragma unroll
        for (int k = 0; k < 20; k++) {
            wif[k] = pk2(SSC * INV_TSC * Wih2[k],  SSC * INV_TSC * Wih2[20 + k]);
            wgo[k] = pk2(Wih2[40 + k],             SSC * INV_TSC * Wih2[60 + k]);
        }
        bif  = pk2(SSC * (bih2[0] + bhh2[0]), SSC * (bih2[1] + bhh2[1]));
        bgo  = pk2(TSC * (bih2[2] + bhh2[2]), SSC * (bih2[3] + bhh2[3]));
        wxif = pk2(SSC * Whh2[0], SSC * Whh2[1]);   // h2-recurrent weights
        wxgo = pk2(TSC * Whh2[2], SSC * Whh2[3]);
    }

    // butterfly-path L2 weights (flush / future phase only); input is TSC*c1
    u64 uif = 0ull, ugo = 0ull;
    if (lane < 20) {
        uif = pk2(SSC * INV_TSC * Wih2[lane],  SSC * INV_TSC * Wih2[20 + lane]);
        ugo = pk2(Wih2[40 + lane],             SSC * INV_TSC * Wih2[60 + lane]);
    }
    const u64 wh2if = pk2(SSC * Whh2[0], SSC * Whh2[1]);
    const u64 wh2go = pk2(TSC * Whh2[2], SSC * Whh2[3]);
    const u64 b2if  = pk2(SSC * (bih2[0] + bhh2[0]), SSC * (bih2[1] + bhh2[1]));
    const u64 b2go  = pk2(TSC * (bih2[2] + bhh2[2]), SSC * (bih2[3] + bhh2[3]));

    // ---- state ----
    float cloc = 0.0f;   // lanes<20: TSC*c1(unit); lane20: TSC*c2
    float hloc = 0.0f;   // lanes<20: h1(unit);     lane20: h2
    int   p    = 0;
    wb[lane]      = 0ull;
    wb[32 + lane] = 0ull;

    // ---- one fused SIMD step; x is the L1 input (lane 20 substitutes hloc) ----
    auto step = [&](float x) {
        const float xl = is20 ? hloc : x;     // SEL, off the carried chain
        __syncwarp();
        const ulonglong2* hp = (const ulonglong2*)(wb + (p << 6) + sec);
        const ulonglong2 v0 = hp[0], v1 = hp[1], v2 = hp[2], v3 = hp[3], v4 = hp[4];
        const ulonglong2 v5 = hp[5], v6 = hp[6], v7 = hp[7], v8 = hp[8], v9 = hp[9];
        const u64 xx = pk2(xl, xl);
        u64 aA = fma2(wif[0], v0.x, fma2(wxif, xx, bif));
        u64 gA = fma2(wgo[0], v0.x, fma2(wxgo, xx, bgo));
        u64 aB = mul2(wif[1], v0.y), gB = mul2(wgo[1], v0.y);
        aA = fma2(wif[2],  v1.x, aA); gA = fma2(wgo[2],  v1.x, gA);
        aB = fma2(wif[3],  v1.y, aB); gB = fma2(wgo[3],  v1.y, gB);
        aA = fma2(wif[4],  v2.x, aA); gA = fma2(wgo[4],  v2.x, gA);
        aB = fma2(wif[5],  v2.y, aB); gB = fma2(wgo[5],  v2.y, gB);
        aA = fma2(wif[6],  v3.x, aA); gA = fma2(wgo[6],  v3.x, gA);
        aB = fma2(wif[7],  v3.y, aB); gB = fma2(wgo[7],  v3.y, gB);
        aA = fma2(wif[8],  v4.x, aA); gA = fma2(wgo[8],  v4.x, gA);
        aB = fma2(wif[9],  v4.y, aB); gB = fma2(wgo[9],  v4.y, gB);
        aA = fma2(wif[10], v5.x, aA); gA = fma2(wgo[10], v5.x, gA);
        aB = fma2(wif[11], v5.y, aB); gB = fma2(wgo[11], v5.y, gB);
        aA = fma2(wif[12], v6.x, aA); gA = fma2(wgo[12], v6.x, gA);
        aB = fma2(wif[13], v6.y, aB); gB = fma2(wgo[13], v6.y, gB);
        aA = fma2(wif[14], v7.x, aA); gA = fma2(wgo[14], v7.x, gA);
        aB = fma2(wif[15], v7.y, aB); gB = fma2(wgo[15], v7.y, gB);
        aA = fma2(wif[16], v8.x, aA); gA = fma2(wgo[16], v8.x, gA);
        aB = fma2(wif[17], v8.y, aB); gB = fma2(wgo[17], v8.y, gB);
        aA = fma2(wif[18], v9.x, aA); gA = fma2(wgo[18], v9.x, gA);
        aB = fma2(wif[19], v9.y, aB); gB = fma2(wgo[19], v9.y, gB);
        const u64 aif = add2(aA, aB), ago = add2(gA, gB);

        float is, fs, gs, os; unpk2(aif, is, fs); unpk2(ago, gs, os);
        // E_f=e^-f, E_g=e^-2g, E_i=e^-i, E_o=e^-o ; chain-critical MUFU first
        const float Ef = ex2a(fs);
        const float Eg = ex2a(gs);
        const float Ei = ex2a(is);
        const float Eo = ex2a(os);

        const float sf  = rcpa(1.0f + Ef);                    // sigmoid(f)
        // TSC * sig(i)*tanh(g) = TSC*(1-Eg) * rcp((1+Eg)*(1+Ei))
        const float igR = rcpa((1.0f + Eg) * (1.0f + Ei));
        const float ig  = fmaf(-TSC, Eg, TSC) * igR;          // keeps TSC scale
        const float t4  = 1.0f + Eo;

        cloc = fmaf(sf, cloc, ig);             // TSC-scaled c update
        u64* sb = wb + ((p ^ 1) << 6);
        sb[32 + lane] = pk2(cloc, cloc);       // c-store early (lane-20's input)

        // sig(o)*tanh(c) = (1-Ec) * rcp((1+Ec)*(1+Eo)),  Ec = e^-2c = ex2(cloc)
        const float Ec = ex2a(cloc);
        hloc = (1.0f - Ec) * rcpa((1.0f + Ec) * t4);
        sb[lane] = pk2(hloc, hloc);
        p ^= 1;
    };

    // ---- butterfly L2 (flush / future phase); c1v is TSC-scaled ----
    auto step_l2 = [&](float c1v, float& c2s, float& h2s) {
        const u64 cc = pk2(c1v, c1v);
        u64 pif = mul2(uif, cc), pgo = mul2(ugo, cc);
#pragma unroll
        for (int m = 16; m; m >>= 1) {
            pif = add2(pif, shfl64(pif, m));
            pgo = add2(pgo, shfl64(pgo, m));
        }
        const u64 hh = pk2(h2s, h2s);
        pif = fma2(wh2if, hh, add2(pif, b2if));
        pgo = fma2(wh2go, hh, add2(pgo, b2go));
        float i2, f2, g2, o2; unpk2(pif, i2, f2); unpk2(pgo, g2, o2);
        const float s2i = sigS(i2), s2f = sigS(f2), t2g = tanhU(g2), s2o = sigS(o2);
        c2s = fmaf(s2f, c2s, s2i * t2g);
        h2s = s2o * tanhU(c2s * TSC);
    };

    const float* xrow = xin + (size_t)b * T;
    float*       orow = out + (size_t)b * (T + F);

    // ---- peel t = 0: L1 only; reset lane-20's (garbage) L2 state ----
    float xn = __ldg(xrow + 1);
    step(__ldg(xrow));
    if (is20) { cloc = 0.0f; hloc = 0.0f; }

    // ---- main loop: fused L1(t) + L2(t-1), zero shuffles ----
#pragma unroll 2
    for (int t = 1; t < T; t++) {
        const float x = xn;
        if (t + 1 < T) xn = __ldg(xrow + t + 1);
        step(x);
        if (is20) orow[t - 1] = cloc * INV_TSC;   // c2(t-1)
    }

    // ---- flush: L2 for step T-1 via butterfly ----
    float c2s = __shfl_sync(0xffffffffu, cloc, 20) * INV_TSC;
    float h2s = __shfl_sync(0xffffffffu, hloc, 20);
    step_l2(cloc, c2s, h2s);                 // cloc = TSC*c1(T-1)
    if (lane == 0) orow[T - 1] = c2s;

    // ---- autoregressive future: strictly sequential ----
#pragma unroll 1
    for (int f = 0; f < F; f++) {
        step(c2s);                            // lanes>=20 results unused
        step_l2(cloc, c2s, h2s);
        if (lane == 0) orow[T + f] = c2s;
    }
}

extern "C" void kernel_launch(void* const* d_in, const int* in_sizes, int n_in,
                              void* d_out, int out_size)
{
    const float* xin  = (const float*)d_in[0];
    const float* Wih1 = (const float*)d_in[1];
    const float* Whh1 = (const float*)d_in[2];
    const float* bih1 = (const float*)d_in[3];
    const float* bhh1 = (const float*)d_in[4];
    const float* Wih2 = (const float*)d_in[5];
    const float* Whh2 = (const float*)d_in[6];
    const float* bih2 = (const float*)d_in[7];
    const float* bhh2 = (const float*)d_in[8];

    const int B = 1024;
    const int T = in_sizes[0] / B;          // 4096
    const int F = out_size / B - T;         // 16

    dim3 grid((B + 3) / 4), block(128);
    lstm_warp_kernel<<<grid, block>>>(xin, Wih1, Whh1, bih1, bhh1,
                                      Wih2, Whh2, bih2, bhh2,
                                      (float*)d_out, B, T, F);
}

// round 11
// speedup vs baseline: 1.0150x; 1.0150x over previous
#include <cuda_runtime.h>

typedef unsigned long long u64;

// ---------- f32x2 packed helpers (Blackwell sm_103a) ----------
__device__ __forceinline__ u64 pk2(float lo, float hi) {
    u64 r; asm("mov.b64 %0,{%1,%2};" : "=l"(r) : "f"(lo), "f"(hi)); return r;
}
__device__ __forceinline__ void unpk2(u64 v, float& lo, float& hi) {
    asm("mov.b64 {%0,%1},%2;" : "=f"(lo), "=f"(hi) : "l"(v));
}
__device__ __forceinline__ u64 fma2(u64 a, u64 b, u64 c) {
    u64 d; asm("fma.rn.f32x2 %0,%1,%2,%3;" : "=l"(d) : "l"(a), "l"(b), "l"(c)); return d;
}
__device__ __forceinline__ u64 add2(u64 a, u64 b) {
    u64 d; asm("add.rn.f32x2 %0,%1,%2;" : "=l"(d) : "l"(a), "l"(b)); return d;
}
__device__ __forceinline__ u64 mul2(u64 a, u64 b) {
    u64 d; asm("mul.rn.f32x2 %0,%1,%2;" : "=l"(d) : "l"(a), "l"(b)); return d;
}
__device__ __forceinline__ u64 shfl64(u64 v, int m) {
    return __shfl_xor_sync(0xffffffffu, v, m);
}

// ---------- activations ----------
__device__ __forceinline__ float ex2a(float x) {
    float y; asm("ex2.approx.f32 %0,%1;" : "=f"(y) : "f"(x)); return y;
}
__device__ __forceinline__ float rcpa(float x) {
    float y; asm("rcp.approx.f32 %0,%1;" : "=f"(y) : "f"(x)); return y;
}
#define SSC (-1.4426950408889634f)     /* -log2(e)   : sigmoid pre-scale */
#define TSC (-2.8853900817779268f)     /* -2*log2(e) : tanh pre-scale    */
#define INV_TSC (-0.3465735902799726f) /* 1/TSC                          */

__device__ __forceinline__ float sigS(float s)  { return rcpa(1.0f + ex2a(s)); }
__device__ __forceinline__ float tanhU(float s) { return fmaf(2.0f, rcpa(1.0f + ex2a(s)), -1.0f); }

// One warp per batch row; cloc carried PRE-SCALED by TSC on all lanes.
// Lanes 0-19: layer-1 unit j=lane (dots over h-section of smem).
// Lane 20   : all four layer-2 gates (dots over c-section, weights /TSC);
//             h2-recurrent term via dedicated wh2A/wh2B fma2s (hh joins the
//             chain at position 2 — NOT at the chain head; R10's SEL-on-head
//             regressed).
// Fused reciprocals: sig(i)*tanh(g) and sig(o)*tanh(c) take ONE rcp each
// -> 8 MUFU/step. c-update keeps TSC scale via ig = fmaf(-TSC,Eg,TSC)*igR.
__global__ void __launch_bounds__(128)
lstm_warp_kernel(const float* __restrict__ xin,
                 const float* __restrict__ Wih1, const float* __restrict__ Whh1,
                 const float* __restrict__ bih1, const float* __restrict__ bhh1,
                 const float* __restrict__ Wih2, const float* __restrict__ Whh2,
                 const float* __restrict__ bih2, const float* __restrict__ bhh2,
                 float* __restrict__ out, int B, int T, int F)
{
    const int w    = threadIdx.x >> 5;
    const int lane = threadIdx.x & 31;
    const int b    = blockIdx.x * 4 + w;

    // [warp][ping][0:32)=(h,h) dup, [32:64)=(TSC*c, TSC*c) dup
    __shared__ __align__(16) u64 sbuf[4][2][64];

    if (b >= B) return;

    const bool is20 = (lane == 20);
    const int  sec  = (lane < 20) ? 0 : 32;
    u64* const wb   = &sbuf[w][0][0];

    // ---- per-lane weights (prescaled); default zero ----
    u64 wif[20], wgo[20];
#pragma unroll
    for (int k = 0; k < 20; k++) { wif[k] = 0ull; wgo[k] = 0ull; }
    u64 wxif = 0ull, wxgo = 0ull, bif = 0ull, bgo = 0ull;
    u64 wh2A = 0ull, wh2B = 0ull;

    if (lane < 20) {
        const int j = lane;
#pragma unroll
        for (int k = 0; k < 20; k++) {
            wif[k] = pk2(SSC * Whh1[j * 20 + k],        SSC * Whh1[(20 + j) * 20 + k]);
            wgo[k] = pk2(TSC * Whh1[(40 + j) * 20 + k], SSC * Whh1[(60 + j) * 20 + k]);
        }
        wxif = pk2(SSC * Wih1[j],      SSC * Wih1[20 + j]);
        wxgo = pk2(TSC * Wih1[40 + j], SSC * Wih1[60 + j]);
        bif  = pk2(SSC * (bih1[j] + bhh1[j]),
                   SSC * (bih1[20 + j] + bhh1[20 + j]));
        bgo  = pk2(TSC * (bih1[40 + j] + bhh1[40 + j]),
                   SSC * (bih1[60 + j] + bhh1[60 + j]));
    } else if (lane == 20) {
        // L2 dots read TSC*c1 -> fold 1/TSC into the weights
#pragma unroll
        for (int k = 0; k < 20; k++) {
            wif[k] = pk2(SSC * INV_TSC * Wih2[k],  SSC * INV_TSC * Wih2[20 + k]);
            wgo[k] = pk2(Wih2[40 + k],             SSC * INV_TSC * Wih2[60 + k]);
        }
        bif  = pk2(SSC * (bih2[0] + bhh2[0]), SSC * (bih2[1] + bhh2[1]));
        bgo  = pk2(TSC * (bih2[2] + bhh2[2]), SSC * (bih2[3] + bhh2[3]));
        wh2A = pk2(SSC * Whh2[0], SSC * Whh2[1]);   // h2 joins at chain pos 2
        wh2B = pk2(TSC * Whh2[2], SSC * Whh2[3]);
    }

    // butterfly-path L2 weights (flush / future phase only); input is TSC*c1
    u64 uif = 0ull, ugo = 0ull;
    if (lane < 20) {
        uif = pk2(SSC * INV_TSC * Wih2[lane],  SSC * INV_TSC * Wih2[20 + lane]);
        ugo = pk2(Wih2[40 + lane],             SSC * INV_TSC * Wih2[60 + lane]);
    }
    const u64 wh2if = pk2(SSC * Whh2[0], SSC * Whh2[1]);
    const u64 wh2go = pk2(TSC * Whh2[2], SSC * Whh2[3]);
    const u64 b2if  = pk2(SSC * (bih2[0] + bhh2[0]), SSC * (bih2[1] + bhh2[1]));
    const u64 b2go  = pk2(TSC * (bih2[2] + bhh2[2]), SSC * (bih2[3] + bhh2[3]));

    // ---- state ----
    float cloc = 0.0f;   // lanes<20: TSC*c1(unit); lane20: TSC*c2
    float hloc = 0.0f;   // lanes<20: h1(unit);     lane20: h2
    int   p    = 0;
    wb[lane]      = 0ull;
    wb[32 + lane] = 0ull;

    // ---- one fused SIMD step ----
    auto step = [&](float x) {
        __syncwarp();
        const ulonglong2* hp = (const ulonglong2*)(wb + (p << 6) + sec);
        const ulonglong2 v0 = hp[0], v1 = hp[1], v2 = hp[2], v3 = hp[3], v4 = hp[4];
        const ulonglong2 v5 = hp[5], v6 = hp[6], v7 = hp[7], v8 = hp[8], v9 = hp[9];
        const u64 xx = pk2(x, x);
        const u64 hh = pk2(hloc, hloc);        // joins at chain position 2
        u64 aA = fma2(wh2A, hh, fma2(wxif, xx, bif));
        u64 gA = fma2(wh2B, hh, fma2(wxgo, xx, bgo));
        u64 aB = mul2(wif[1], v0.y), gB = mul2(wgo[1], v0.y);
        aA = fma2(wif[0],  v0.x, aA); gA = fma2(wgo[0],  v0.x, gA);
        aB = fma2(wif[3],  v1.y, aB); gB = fma2(wgo[3],  v1.y, gB);
        aA = fma2(wif[2],  v1.x, aA); gA = fma2(wgo[2],  v1.x, gA);
        aB = fma2(wif[5],  v2.y, aB); gB = fma2(wgo[5],  v2.y, gB);
        aA = fma2(wif[4],  v2.x, aA); gA = fma2(wgo[4],  v2.x, gA);
        aB = fma2(wif[7],  v3.y, aB); gB = fma2(wgo[7],  v3.y, gB);
        aA = fma2(wif[6],  v3.x, aA); gA = fma2(wgo[6],  v3.x, gA);
        aB = fma2(wif[9],  v4.y, aB); gB = fma2(wgo[9],  v4.y, gB);
        aA = fma2(wif[8],  v4.x, aA); gA = fma2(wgo[8],  v4.x, gA);
        aB = fma2(wif[11], v5.y, aB); gB = fma2(wgo[11], v5.y, gB);
        aA = fma2(wif[10], v5.x, aA); gA = fma2(wgo[10], v5.x, gA);
        aB = fma2(wif[13], v6.y, aB); gB = fma2(wgo[13], v6.y, gB);
        aA = fma2(wif[12], v6.x, aA); gA = fma2(wgo[12], v6.x, gA);
        aB = fma2(wif[15], v7.y, aB); gB = fma2(wgo[15], v7.y, gB);
        aA = fma2(wif[14], v7.x, aA); gA = fma2(wgo[14], v7.x, gA);
        aB = fma2(wif[17], v8.y, aB); gB = fma2(wgo[17], v8.y, gB);
        aA = fma2(wif[16], v8.x, aA); gA = fma2(wgo[16], v8.x, gA);
        aB = fma2(wif[19], v9.y, aB); gB = fma2(wgo[19], v9.y, gB);
        aA = fma2(wif[18], v9.x, aA); gA = fma2(wgo[18], v9.x, gA);
        const u64 aif = add2(aA, aB), ago = add2(gA, gB);

        float is, fs, gs, os; unpk2(aif, is, fs); unpk2(ago, gs, os);
        // E_f=e^-f, E_g=e^-2g, E_i=e^-i, E_o=e^-o ; chain-critical MUFU first
        const float Ef = ex2a(fs);
        const float Eg = ex2a(gs);
        const float Ei = ex2a(is);
        const float Eo = ex2a(os);

        const float sf  = rcpa(1.0f + Ef);                    // sigmoid(f)
        // TSC*sig(i)*tanh(g) = TSC*(1-Eg) * rcp((1+Eg)*(1+Ei))
        const float igR = rcpa((1.0f + Eg) * (1.0f + Ei));
        const float ig  = fmaf(-TSC, Eg, TSC) * igR;
        const float t4  = 1.0f + Eo;

        cloc = fmaf(sf, cloc, ig);             // TSC-scaled c update
        u64* sb = wb + ((p ^ 1) << 6);
        sb[32 + lane] = pk2(cloc, cloc);       // c-store early (lane-20's input)

        // sig(o)*tanh(c) = (1-Ec) * rcp((1+Ec)*(1+Eo)),  Ec = ex2(cloc)
        const float Ec = ex2a(cloc);
        hloc = (1.0f - Ec) * rcpa((1.0f + Ec) * t4);
        sb[lane] = pk2(hloc, hloc);
        p ^= 1;
    };

    // ---- butterfly L2 (flush / future phase); c1v is TSC-scaled ----
    auto step_l2 = [&](float c1v, float& c2s, float& h2s) {
        const u64 cc = pk2(c1v, c1v);
        u64 pif = mul2(uif, cc), pgo = mul2(ugo, cc);
#pragma unroll
        for (int m = 16; m; m >>= 1) {
            pif = add2(pif, shfl64(pif, m));
            pgo = add2(pgo, shfl64(pgo, m));
        }
        const u64 hh = pk2(h2s, h2s);
        pif = fma2(wh2if, hh, add2(pif, b2if));
        pgo = fma2(wh2go, hh, add2(pgo, b2go));
        float i2, f2, g2, o2; unpk2(pif, i2, f2); unpk2(pgo, g2, o2);
        const float s2i = sigS(i2), s2f = sigS(f2), t2g = tanhU(g2), s2o = sigS(o2);
        c2s = fmaf(s2f, c2s, s2i * t2g);
        h2s = s2o * tanhU(c2s * TSC);
    };

    const float* xrow = xin + (size_t)b * T;
    float*       orow = out + (size_t)b * (T + F);

    // ---- peel t = 0: L1 only; reset lane-20's (garbage) L2 state ----
    float xn = __ldg(xrow + 1);
    step(__ldg(xrow));
    if (is20) { cloc = 0.0f; hloc = 0.0f; }

    // ---- main loop: fused L1(t) + L2(t-1), zero shuffles ----
#pragma unroll 1
    for (int t = 1; t < T; t++) {
        const float x = xn;
        if (t + 1 < T) xn = __ldg(xrow + t + 1);
        step(x);
        if (is20) orow[t - 1] = cloc * INV_TSC;   // c2(t-1)
    }

    // ---- flush: L2 for step T-1 via butterfly ----
    float c2s = __shfl_sync(0xffffffffu, cloc, 20) * INV_TSC;
    float h2s = __shfl_sync(0xffffffffu, hloc, 20);
    step_l2(cloc, c2s, h2s);                 // cloc = TSC*c1(T-1)
    if (lane == 0) orow[T - 1] = c2s;

    // ---- autoregressive future: strictly sequential ----
#pragma unroll 1
    for (int f = 0; f < F; f++) {
        step(c2s);                            // lanes>=20 results unused
        step_l2(cloc, c2s, h2s);
        if (lane == 0) orow[T + f] = c2s;
    }
}

extern "C" void kernel_launch(void* const* d_in, const int* in_sizes, int n_in,
                              void* d_out, int out_size)
{
    const float* xin  = (const float*)d_in[0];
    const float* Wih1 = (const float*)d_in[1];
    const float* Whh1 = (const float*)d_in[2];
    const float* bih1 = (const float*)d_in[3];
    const float* bhh1 = (const float*)d_in[4];
    const float* Wih2 = (const float*)d_in[5];
    const float* Whh2 = (const float*)d_in[6];
    const float* bih2 = (const float*)d_in[7];
    const float* bhh2 = (const float*)d_in[8];

    const int B = 1024;
    const int T = in_sizes[0] / B;          // 4096
    const int F = out_size / B - T;         // 16

    dim3 grid((B + 3) / 4), block(128);
    lstm_warp_kernel<<<grid, block>>>(xin, Wih1, Whh1, bih1, bhh1,
                                      Wih2, Whh2, bih2, bhh2,
                                      (float*)d_out, B, T, F);
}

// round 12
// speedup vs baseline: 1.0333x; 1.0181x over previous
#include <cuda_runtime.h>

typedef unsigned long long u64;

// ---------- f32x2 packed helpers (Blackwell sm_103a) ----------
__device__ __forceinline__ u64 pk2(float lo, float hi) {
    u64 r; asm("mov.b64 %0,{%1,%2};" : "=l"(r) : "f"(lo), "f"(hi)); return r;
}
__device__ __forceinline__ void unpk2(u64 v, float& lo, float& hi) {
    asm("mov.b64 {%0,%1},%2;" : "=f"(lo), "=f"(hi) : "l"(v));
}
__device__ __forceinline__ u64 fma2(u64 a, u64 b, u64 c) {
    u64 d; asm("fma.rn.f32x2 %0,%1,%2,%3;" : "=l"(d) : "l"(a), "l"(b), "l"(c)); return d;
}
__device__ __forceinline__ u64 add2(u64 a, u64 b) {
    u64 d; asm("add.rn.f32x2 %0,%1,%2;" : "=l"(d) : "l"(a), "l"(b)); return d;
}
__device__ __forceinline__ u64 mul2(u64 a, u64 b) {
    u64 d; asm("mul.rn.f32x2 %0,%1,%2;" : "=l"(d) : "l"(a), "l"(b)); return d;
}
__device__ __forceinline__ u64 shfl64(u64 v, int m) {
    return __shfl_xor_sync(0xffffffffu, v, m);
}

// ---------- activations (R7 structure — empirically best) ----------
__device__ __forceinline__ float ex2a(float x) {
    float y; asm("ex2.approx.f32 %0,%1;" : "=f"(y) : "f"(x)); return y;
}
__device__ __forceinline__ float rcpa(float x) {
    float y; asm("rcp.approx.f32 %0,%1;" : "=f"(y) : "f"(x)); return y;
}
#define SSC (-1.4426950408889634f)     /* -log2(e)   : sigmoid pre-scale */
#define TSC (-2.8853900817779268f)     /* -2*log2(e) : tanh pre-scale    */
#define INV_TSC (-0.3465735902799726f) /* 1/TSC                          */

__device__ __forceinline__ float sigS(float s)  { return rcpa(1.0f + ex2a(s)); }
__device__ __forceinline__ float tanhU(float s) { return fmaf(2.0f, rcpa(1.0f + ex2a(s)), -1.0f); }

// One warp per batch row; cloc carried PRE-SCALED by TSC on all lanes.
// h/c stored in smem as PLAIN floats (no duplication). Each gate has its own
// f32x2 accumulator over (even-k, odd-k) partitions, so a ulonglong2 load of
// the float array feeds fma2 directly: 5 LDS.128/step instead of 10.
// Lanes 0-19: layer-1 unit j=lane (h-section). Lane 20: all four layer-2
// gates (c-section, weights /TSC); x-operand slot (x,hloc) carries x for
// lanes<20 and h2 for lane 20 via per-lane (wx,wh2) packing.
// No __syncwarp in the loop: zero divergence; per-warp in-order LSU ordering
// guarantees the prior STS lands before the next LDS.
__global__ void __launch_bounds__(128)
lstm_warp_kernel(const float* __restrict__ xin,
                 const float* __restrict__ Wih1, const float* __restrict__ Whh1,
                 const float* __restrict__ bih1, const float* __restrict__ bhh1,
                 const float* __restrict__ Wih2, const float* __restrict__ Whh2,
                 const float* __restrict__ bih2, const float* __restrict__ bhh2,
                 float* __restrict__ out, int B, int T, int F)
{
    const int w    = threadIdx.x >> 5;
    const int lane = threadIdx.x & 31;
    const int b    = blockIdx.x * 4 + w;

    // [warp][ping][0:20)=h floats, [32:52)=TSC*c floats (64-float pings)
    __shared__ __align__(16) float fbuf[4][2][64];

    if (b >= B) return;

    const bool is20 = (lane == 20);
    const int  sec  = (lane < 20) ? 0 : 32;      // float index of read section
    float* const wb = &fbuf[w][0][0];

    // ---- per-lane weights: per-gate even/odd pairs; default zero ----
    u64 wi[10], wf[10], wg[10], wo[10];
#pragma unroll
    for (int m = 0; m < 10; m++) { wi[m] = wf[m] = wg[m] = wo[m] = 0ull; }
    u64 wxi = 0ull, wxf = 0ull, wxg = 0ull, wxo = 0ull;
    u64 bi = 0ull, bf = 0ull, bg = 0ull, bo = 0ull;

    if (lane < 20) {
        const int j = lane;
#pragma unroll
        for (int m = 0; m < 10; m++) {
            wi[m] = pk2(SSC * Whh1[j * 20 + 2 * m],        SSC * Whh1[j * 20 + 2 * m + 1]);
            wf[m] = pk2(SSC * Whh1[(20 + j) * 20 + 2 * m], SSC * Whh1[(20 + j) * 20 + 2 * m + 1]);
            wg[m] = pk2(TSC * Whh1[(40 + j) * 20 + 2 * m], TSC * Whh1[(40 + j) * 20 + 2 * m + 1]);
            wo[m] = pk2(SSC * Whh1[(60 + j) * 20 + 2 * m], SSC * Whh1[(60 + j) * 20 + 2 * m + 1]);
        }
        wxi = pk2(SSC * Wih1[j],      0.0f);
        wxf = pk2(SSC * Wih1[20 + j], 0.0f);
        wxg = pk2(TSC * Wih1[40 + j], 0.0f);
        wxo = pk2(SSC * Wih1[60 + j], 0.0f);
        bi  = pk2(SSC * (bih1[j] + bhh1[j]),           0.0f);
        bf  = pk2(SSC * (bih1[20 + j] + bhh1[20 + j]), 0.0f);
        bg  = pk2(TSC * (bih1[40 + j] + bhh1[40 + j]), 0.0f);
        bo  = pk2(SSC * (bih1[60 + j] + bhh1[60 + j]), 0.0f);
    } else if (lane == 20) {
        // L2 dots read TSC*c1 -> fold 1/TSC (g-gate: TSC*INV_TSC = 1)
#pragma unroll
        for (int m = 0; m < 10; m++) {
            wi[m] = pk2(SSC * INV_TSC * Wih2[2 * m],      SSC * INV_TSC * Wih2[2 * m + 1]);
            wf[m] = pk2(SSC * INV_TSC * Wih2[20 + 2 * m], SSC * INV_TSC * Wih2[20 + 2 * m + 1]);
            wg[m] = pk2(Wih2[40 + 2 * m],                 Wih2[40 + 2 * m + 1]);
            wo[m] = pk2(SSC * INV_TSC * Wih2[60 + 2 * m], SSC * INV_TSC * Wih2[60 + 2 * m + 1]);
        }
        // x-slot operand is (x, hloc): hi half carries h2 * wh2
        wxi = pk2(0.0f, SSC * Whh2[0]);
        wxf = pk2(0.0f, SSC * Whh2[1]);
        wxg = pk2(0.0f, TSC * Whh2[2]);
        wxo = pk2(0.0f, SSC * Whh2[3]);
        bi  = pk2(SSC * (bih2[0] + bhh2[0]), 0.0f);
        bf  = pk2(SSC * (bih2[1] + bhh2[1]), 0.0f);
        bg  = pk2(TSC * (bih2[2] + bhh2[2]), 0.0f);
        bo  = pk2(SSC * (bih2[3] + bhh2[3]), 0.0f);
    }

    // butterfly-path L2 weights (flush / future phase only); input is TSC*c1
    u64 uif = 0ull, ugo = 0ull;
    if (lane < 20) {
        uif = pk2(SSC * INV_TSC * Wih2[lane],  SSC * INV_TSC * Wih2[20 + lane]);
        ugo = pk2(Wih2[40 + lane],             SSC * INV_TSC * Wih2[60 + lane]);
    }
    const u64 wh2if = pk2(SSC * Whh2[0], SSC * Whh2[1]);
    const u64 wh2go = pk2(TSC * Whh2[2], SSC * Whh2[3]);
    const u64 b2if  = pk2(SSC * (bih2[0] + bhh2[0]), SSC * (bih2[1] + bhh2[1]));
    const u64 b2go  = pk2(TSC * (bih2[2] + bhh2[2]), SSC * (bih2[3] + bhh2[3]));

    // ---- state ----
    float cloc = 0.0f;   // lanes<20: TSC*c1(unit); lane20: TSC*c2
    float hloc = 0.0f;   // lanes<20: h1(unit);     lane20: h2
    int   p    = 0;
#pragma unroll
    for (int k = lane; k < 64; k += 32) wb[k] = 0.0f;   // zero ping 0

    // ---- one fused SIMD step (no syncwarp: in-order LSU per warp) ----
    auto step = [&](float x) {
        const u64 xh = pk2(x, hloc);   // lo: x-term (lanes<20), hi: h2 (lane20)
        u64 ai = fma2(wxi, xh, bi);
        u64 af = fma2(wxf, xh, bf);
        u64 ag = fma2(wxg, xh, bg);
        u64 ao = fma2(wxo, xh, bo);
        const ulonglong2* hp = (const ulonglong2*)(wb + (p << 6) + sec);
        const ulonglong2 v0 = hp[0], v1 = hp[1], v2 = hp[2], v3 = hp[3], v4 = hp[4];
        ai = fma2(wi[0], v0.x, ai);  af = fma2(wf[0], v0.x, af);
        ag = fma2(wg[0], v0.x, ag);  ao = fma2(wo[0], v0.x, ao);
        ai = fma2(wi[1], v0.y, ai);  af = fma2(wf[1], v0.y, af);
        ag = fma2(wg[1], v0.y, ag);  ao = fma2(wo[1], v0.y, ao);
        ai = fma2(wi[2], v1.x, ai);  af = fma2(wf[2], v1.x, af);
        ag = fma2(wg[2], v1.x, ag);  ao = fma2(wo[2], v1.x, ao);
        ai = fma2(wi[3], v1.y, ai);  af = fma2(wf[3], v1.y, af);
        ag = fma2(wg[3], v1.y, ag);  ao = fma2(wo[3], v1.y, ao);
        ai = fma2(wi[4], v2.x, ai);  af = fma2(wf[4], v2.x, af);
        ag = fma2(wg[4], v2.x, ag);  ao = fma2(wo[4], v2.x, ao);
        ai = fma2(wi[5], v2.y, ai);  af = fma2(wf[5], v2.y, af);
        ag = fma2(wg[5], v2.y, ag);  ao = fma2(wo[5], v2.y, ao);
        ai = fma2(wi[6], v3.x, ai);  af = fma2(wf[6], v3.x, af);
        ag = fma2(wg[6], v3.x, ag);  ao = fma2(wo[6], v3.x, ao);
        ai = fma2(wi[7], v3.y, ai);  af = fma2(wf[7], v3.y, af);
        ag = fma2(wg[7], v3.y, ag);  ao = fma2(wo[7], v3.y, ao);
        ai = fma2(wi[8], v4.x, ai);  af = fma2(wf[8], v4.x, af);
        ag = fma2(wg[8], v4.x, ag);  ao = fma2(wo[8], v4.x, ao);
        ai = fma2(wi[9], v4.y, ai);  af = fma2(wf[9], v4.y, af);
        ag = fma2(wg[9], v4.y, ag);  ao = fma2(wo[9], v4.y, ao);

        float i0, i1, f0, f1, g0, g1, o0, o1;
        unpk2(ai, i0, i1); unpk2(af, f0, f1);
        unpk2(ag, g0, g1); unpk2(ao, o0, o1);
        const float fs = f0 + f1;
        const float gs = g0 + g1;
        const float is = i0 + i1;
        const float os = o0 + o1;

        // R7 activation structure, chain-critical MUFU first
        const float Ef = ex2a(fs);
        const float Eg = ex2a(gs);
        const float Ei = ex2a(is);
        const float sf  = rcpa(1.0f + Ef);                        // sigmoid(f)
        const float tgT = fmaf(2.0f * TSC, rcpa(1.0f + Eg), -TSC);// TSC*tanh(g)
        const float si  = rcpa(1.0f + Ei);                        // sigmoid(i)
        const float Eo = ex2a(os);
        const float so = rcpa(1.0f + Eo);                         // sigmoid(o)

        cloc = fmaf(sf, cloc, si * tgT);                 // TSC-scaled c update
        hloc = so * fmaf(2.0f, rcpa(1.0f + ex2a(cloc)), -1.0f);

        float* sb = wb + ((p ^ 1) << 6);
        sb[lane]      = hloc;                            // STS.32
        sb[32 + lane] = cloc;                            // STS.32
        p ^= 1;
    };

    // ---- butterfly L2 (flush / future phase); c1v is TSC-scaled ----
    auto step_l2 = [&](float c1v, float& c2s, float& h2s) {
        const u64 cc = pk2(c1v, c1v);
        u64 pif = mul2(uif, cc), pgo = mul2(ugo, cc);
#pragma unroll
        for (int m = 16; m; m >>= 1) {
            pif = add2(pif, shfl64(pif, m));
            pgo = add2(pgo, shfl64(pgo, m));
        }
        const u64 hh = pk2(h2s, h2s);
        pif = fma2(wh2if, hh, add2(pif, b2if));
        pgo = fma2(wh2go, hh, add2(pgo, b2go));
        float i2, f2, g2, o2; unpk2(pif, i2, f2); unpk2(pgo, g2, o2);
        const float s2i = sigS(i2), s2f = sigS(f2), t2g = tanhU(g2), s2o = sigS(o2);
        c2s = fmaf(s2f, c2s, s2i * t2g);
        h2s = s2o * tanhU(c2s * TSC);
    };

    const float* xrow = xin + (size_t)b * T;
    float*       orow = out + (size_t)b * (T + F);

    // ---- peel t = 0: L1 only; reset lane-20's (garbage) L2 state ----
    float xn = __ldg(xrow + 1);
    step(__ldg(xrow));
    if (is20) { cloc = 0.0f; hloc = 0.0f; }

    // ---- main loop: fused L1(t) + L2(t-1), zero shuffles, zero syncs ----
#pragma unroll 1
    for (int t = 1; t < T; t++) {
        const float x = xn;
        if (t + 1 < T) xn = __ldg(xrow + t + 1);
        step(x);
        if (is20) orow[t - 1] = cloc * INV_TSC;   // c2(t-1)
    }

    // ---- flush: L2 for step T-1 via butterfly ----
    float c2s = __shfl_sync(0xffffffffu, cloc, 20) * INV_TSC;
    float h2s = __shfl_sync(0xffffffffu, hloc, 20);
    step_l2(cloc, c2s, h2s);                 // cloc = TSC*c1(T-1)
    if (lane == 0) orow[T - 1] = c2s;

    // ---- autoregressive future: strictly sequential ----
#pragma unroll 1
    for (int f = 0; f < F; f++) {
        step(c2s);                            // lanes>=20 results unused
        step_l2(cloc, c2s, h2s);
        if (lane == 0) orow[T + f] = c2s;
    }
}

extern "C" void kernel_launch(void* const* d_in, const int* in_sizes, int n_in,
                              void* d_out, int out_size)
{
    const float* xin  = (const float*)d_in[0];
    const float* Wih1 = (const float*)d_in[1];
    const float* Whh1 = (const float*)d_in[2];
    const float* bih1 = (const float*)d_in[3];
    const float* bhh1 = (const float*)d_in[4];
    const float* Wih2 = (const float*)d_in[5];
    const float* Whh2 = (const float*)d_in[6];
    const float* bih2 = (const float*)d_in[7];
    const float* bhh2 = (const float*)d_in[8];

    const int B = 1024;
    const int T = in_sizes[0] / B;          // 4096
    const int F = out_size / B - T;         // 16

    dim3 grid((B + 3) / 4), block(128);
    lstm_warp_kernel<<<grid, block>>>(xin, Wih1, Whh1, bih1, bhh1,
                                      Wih2, Whh2, bih2, bhh2,
                                      (float*)d_out, B, T, F);
}

// round 13
// speedup vs baseline: 1.0532x; 1.0192x over previous
#include <cuda_runtime.h>

typedef unsigned long long u64;

// ---------- f32x2 packed helpers (Blackwell sm_103a) ----------
__device__ __forceinline__ u64 pk2(float lo, float hi) {
    u64 r; asm("mov.b64 %0,{%1,%2};" : "=l"(r) : "f"(lo), "f"(hi)); return r;
}
__device__ __forceinline__ void unpk2(u64 v, float& lo, float& hi) {
    asm("mov.b64 {%0,%1},%2;" : "=f"(lo), "=f"(hi) : "l"(v));
}
__device__ __forceinline__ u64 fma2(u64 a, u64 b, u64 c) {
    u64 d; asm("fma.rn.f32x2 %0,%1,%2,%3;" : "=l"(d) : "l"(a), "l"(b), "l"(c)); return d;
}
__device__ __forceinline__ u64 add2(u64 a, u64 b) {
    u64 d; asm("add.rn.f32x2 %0,%1,%2;" : "=l"(d) : "l"(a), "l"(b)); return d;
}
__device__ __forceinline__ u64 mul2(u64 a, u64 b) {
    u64 d; asm("mul.rn.f32x2 %0,%1,%2;" : "=l"(d) : "l"(a), "l"(b)); return d;
}
__device__ __forceinline__ u64 shfl64(u64 v, int m) {
    return __shfl_xor_sync(0xffffffffu, v, m);
}

// ---------- activations (R7 structure — empirically best) ----------
__device__ __forceinline__ float ex2a(float x) {
    float y; asm("ex2.approx.f32 %0,%1;" : "=f"(y) : "f"(x)); return y;
}
__device__ __forceinline__ float rcpa(float x) {
    float y; asm("rcp.approx.f32 %0,%1;" : "=f"(y) : "f"(x)); return y;
}
#define SSC (-1.4426950408889634f)     /* -log2(e)   : sigmoid pre-scale */
#define TSC (-2.8853900817779268f)     /* -2*log2(e) : tanh pre-scale    */
#define INV_TSC (-0.3465735902799726f) /* 1/TSC                          */

__device__ __forceinline__ float sigS(float s)  { return rcpa(1.0f + ex2a(s)); }
__device__ __forceinline__ float tanhU(float s) { return fmaf(2.0f, rcpa(1.0f + ex2a(s)), -1.0f); }

// One warp per batch row; cloc carried PRE-SCALED by TSC on all lanes.
// Lanes 0-19: layer-1 unit j=lane, (i,f) in aif, (g,o) in ago, dots over the
// h-section of smem. Lane 20: all four layer-2 gates (dots over c-section,
// weights /TSC); h2-recurrent term via wh2A/wh2B fma2s joining at chain pos 2
// (NOT the chain head — R10/R12 regressions).
// R13 deltas vs R7 (1046.6us): (1) no __syncwarp in the loop — within-warp
// in-order LSU ordering validated correct by R12's full-length pass;
// (2) cloc stored immediately after its fmaf so lane-20's next-step input
// lands in smem earlier. Everything else verbatim R7.
__global__ void __launch_bounds__(128)
lstm_warp_kernel(const float* __restrict__ xin,
                 const float* __restrict__ Wih1, const float* __restrict__ Whh1,
                 const float* __restrict__ bih1, const float* __restrict__ bhh1,
                 const float* __restrict__ Wih2, const float* __restrict__ Whh2,
                 const float* __restrict__ bih2, const float* __restrict__ bhh2,
                 float* __restrict__ out, int B, int T, int F)
{
    const int w    = threadIdx.x >> 5;
    const int lane = threadIdx.x & 31;
    const int b    = blockIdx.x * 4 + w;

    // [warp][ping][0:32)=(h,h) dup, [32:64)=(TSC*c, TSC*c) dup
    __shared__ __align__(16) u64 sbuf[4][2][64];

    if (b >= B) return;

    const bool is20 = (lane == 20);
    const int  sec  = (lane < 20) ? 0 : 32;
    u64* const wb   = &sbuf[w][0][0];

    // ---- per-lane weights (prescaled); default zero ----
    u64 wif[20], wgo[20];
#pragma unroll
    for (int k = 0; k < 20; k++) { wif[k] = 0ull; wgo[k] = 0ull; }
    u64 wxif = 0ull, wxgo = 0ull, bif = 0ull, bgo = 0ull;
    u64 wh2A = 0ull, wh2B = 0ull;

    if (lane < 20) {
        const int j = lane;
#pragma unroll
        for (int k = 0; k < 20; k++) {
            wif[k] = pk2(SSC * Whh1[j * 20 + k],        SSC * Whh1[(20 + j) * 20 + k]);
            wgo[k] = pk2(TSC * Whh1[(40 + j) * 20 + k], SSC * Whh1[(60 + j) * 20 + k]);
        }
        wxif = pk2(SSC * Wih1[j],      SSC * Wih1[20 + j]);
        wxgo = pk2(TSC * Wih1[40 + j], SSC * Wih1[60 + j]);
        bif  = pk2(SSC * (bih1[j] + bhh1[j]),
                   SSC * (bih1[20 + j] + bhh1[20 + j]));
        bgo  = pk2(TSC * (bih1[40 + j] + bhh1[40 + j]),
                   SSC * (bih1[60 + j] + bhh1[60 + j]));
    } else if (lane == 20) {
        // L2 dots read TSC*c1 -> fold 1/TSC into the weights
#pragma unroll
        for (int k = 0; k < 20; k++) {
            wif[k] = pk2(SSC * INV_TSC * Wih2[k],  SSC * INV_TSC * Wih2[20 + k]);
            wgo[k] = pk2(Wih2[40 + k],             SSC * INV_TSC * Wih2[60 + k]);
        }
        bif  = pk2(SSC * (bih2[0] + bhh2[0]), SSC * (bih2[1] + bhh2[1]));
        bgo  = pk2(TSC * (bih2[2] + bhh2[2]), SSC * (bih2[3] + bhh2[3]));
        wh2A = pk2(SSC * Whh2[0], SSC * Whh2[1]);   // h2 joins at chain pos 2
        wh2B = pk2(TSC * Whh2[2], SSC * Whh2[3]);
    }

    // butterfly-path L2 weights (flush / future phase only); input is TSC*c1
    u64 uif = 0ull, ugo = 0ull;
    if (lane < 20) {
        uif = pk2(SSC * INV_TSC * Wih2[lane],  SSC * INV_TSC * Wih2[20 + lane]);
        ugo = pk2(Wih2[40 + lane],             SSC * INV_TSC * Wih2[60 + lane]);
    }
    const u64 wh2if = pk2(SSC * Whh2[0], SSC * Whh2[1]);
    const u64 wh2go = pk2(TSC * Whh2[2], SSC * Whh2[3]);
    const u64 b2if  = pk2(SSC * (bih2[0] + bhh2[0]), SSC * (bih2[1] + bhh2[1]));
    const u64 b2go  = pk2(TSC * (bih2[2] + bhh2[2]), SSC * (bih2[3] + bhh2[3]));

    // ---- state ----
    float cloc = 0.0f;   // lanes<20: TSC*c1(unit); lane20: TSC*c2
    float hloc = 0.0f;   // lanes<20: h1(unit);     lane20: h2
    int   p    = 0;
    wb[lane]      = 0ull;
    wb[32 + lane] = 0ull;

    // ---- one fused SIMD step (no syncwarp: in-order LSU per warp) ----
    auto step = [&](float x) {
        const ulonglong2* hp = (const ulonglong2*)(wb + (p << 6) + sec);
        const ulonglong2 v0 = hp[0], v1 = hp[1], v2 = hp[2], v3 = hp[3], v4 = hp[4];
        const ulonglong2 v5 = hp[5], v6 = hp[6], v7 = hp[7], v8 = hp[8], v9 = hp[9];
        const u64 xx = pk2(x, x);
        const u64 hh = pk2(hloc, hloc);        // joins at chain position 2
        u64 aA = fma2(wh2A, hh, fma2(wxif, xx, bif));
        u64 gA = fma2(wh2B, hh, fma2(wxgo, xx, bgo));
        u64 aB = mul2(wif[1], v0.y), gB = mul2(wgo[1], v0.y);
        aA = fma2(wif[0],  v0.x, aA); gA = fma2(wgo[0],  v0.x, gA);
        aB = fma2(wif[3],  v1.y, aB); gB = fma2(wgo[3],  v1.y, gB);
        aA = fma2(wif[2],  v1.x, aA); gA = fma2(wgo[2],  v1.x, gA);
        aB = fma2(wif[5],  v2.y, aB); gB = fma2(wgo[5],  v2.y, gB);
        aA = fma2(wif[4],  v2.x, aA); gA = fma2(wgo[4],  v2.x, gA);
        aB = fma2(wif[7],  v3.y, aB); gB = fma2(wgo[7],  v3.y, gB);
        aA = fma2(wif[6],  v3.x, aA); gA = fma2(wgo[6],  v3.x, gA);
        aB = fma2(wif[9],  v4.y, aB); gB = fma2(wgo[9],  v4.y, gB);
        aA = fma2(wif[8],  v4.x, aA); gA = fma2(wgo[8],  v4.x, gA);
        aB = fma2(wif[11], v5.y, aB); gB = fma2(wgo[11], v5.y, gB);
        aA = fma2(wif[10], v5.x, aA); gA = fma2(wgo[10], v5.x, gA);
        aB = fma2(wif[13], v6.y, aB); gB = fma2(wgo[13], v6.y, gB);
        aA = fma2(wif[12], v6.x, aA); gA = fma2(wgo[12], v6.x, gA);
        aB = fma2(wif[15], v7.y, aB); gB = fma2(wgo[15], v7.y, gB);
        aA = fma2(wif[14], v7.x, aA); gA = fma2(wgo[14], v7.x, gA);
        aB = fma2(wif[17], v8.y, aB); gB = fma2(wgo[17], v8.y, gB);
        aA = fma2(wif[16], v8.x, aA); gA = fma2(wgo[16], v8.x, gA);
        aB = fma2(wif[19], v9.y, aB); gB = fma2(wgo[19], v9.y, gB);
        aA = fma2(wif[18], v9.x, aA); gA = fma2(wgo[18], v9.x, gA);
        const u64 aif = add2(aA, aB), ago = add2(gA, gB);

        float is, fs, gs, os; unpk2(aif, is, fs); unpk2(ago, gs, os);
        const float ei = ex2a(is), ef = ex2a(fs), eg = ex2a(gs), eo = ex2a(os);
        const float si  = rcpa(1.0f + ei), sf = rcpa(1.0f + ef);
        const float tgT = fmaf(2.0f * TSC, rcpa(1.0f + eg), -TSC);  // TSC*tanh
        const float so  = rcpa(1.0f + eo);

        cloc = fmaf(sf, cloc, si * tgT);       // TSC-scaled c update
        u64* sb = wb + ((p ^ 1) << 6);
        sb[32 + lane] = pk2(cloc, cloc);       // c-store early (lane-20's input)
        hloc = so * tanhU(cloc);               // EX2 directly on scaled c
        sb[lane] = pk2(hloc, hloc);
        p ^= 1;
    };

    // ---- butterfly L2 (flush / future phase); c1v is TSC-scaled ----
    auto step_l2 = [&](float c1v, float& c2s, float& h2s) {
        const u64 cc = pk2(c1v, c1v);
        u64 pif = mul2(uif, cc), pgo = mul2(ugo, cc);
#pragma unroll
        for (int m = 16; m; m >>= 1) {
            pif = add2(pif, shfl64(pif, m));
            pgo = add2(pgo, shfl64(pgo, m));
        }
        const u64 hh = pk2(h2s, h2s);
        pif = fma2(wh2if, hh, add2(pif, b2if));
        pgo = fma2(wh2go, hh, add2(pgo, b2go));
        float i2, f2, g2, o2; unpk2(pif, i2, f2); unpk2(pgo, g2, o2);
        const float s2i = sigS(i2), s2f = sigS(f2), t2g = tanhU(g2), s2o = sigS(o2);
        c2s = fmaf(s2f, c2s, s2i * t2g);
        h2s = s2o * tanhU(c2s * TSC);
    };

    const float* xrow = xin + (size_t)b * T;
    float*       orow = out + (size_t)b * (T + F);

    // ---- peel t = 0: L1 only; reset lane-20's (garbage) L2 state ----
    float xn = __ldg(xrow + 1);
    step(__ldg(xrow));
    if (is20) { cloc = 0.0f; hloc = 0.0f; }

    // ---- main loop: fused L1(t) + L2(t-1), zero shuffles, zero syncs ----
#pragma unroll 1
    for (int t = 1; t < T; t++) {
        const float x = xn;
        if (t + 1 < T) xn = __ldg(xrow + t + 1);
        step(x);
        if (is20) orow[t - 1] = cloc * INV_TSC;   // c2(t-1)
    }

    // ---- flush: L2 for step T-1 via butterfly ----
    float c2s = __shfl_sync(0xffffffffu, cloc, 20) * INV_TSC;
    float h2s = __shfl_sync(0xffffffffu, hloc, 20);
    step_l2(cloc, c2s, h2s);                 // cloc = TSC*c1(T-1)
    if (lane == 0) orow[T - 1] = c2s;

    // ---- autoregressive future: strictly sequential ----
#pragma unroll 1
    for (int f = 0; f < F; f++) {
        step(c2s);                            // lanes>=20 results unused
        step_l2(cloc, c2s, h2s);
        if (lane == 0) orow[T + f] = c2s;
    }
}

extern "C" void kernel_launch(void* const* d_in, const int* in_sizes, int n_in,
                              void* d_out, int out_size)
{
    const float* xin  = (const float*)d_in[0];
    const float* Wih1 = (const float*)d_in[1];
    const float* Whh1 = (const float*)d_in[2];
    const float* bih1 = (const float*)d_in[3];
    const float* bhh1 = (const float*)d_in[4];
    const float* Wih2 = (const float*)d_in[5];
    const float* Whh2 = (const float*)d_in[6];
    const float* bih2 = (const float*)d_in[7];
    const float* bhh2 = (const float*)d_in[8];

    const int B = 1024;
    const int T = in_sizes[0] / B;          // 4096
    const int F = out_size / B - T;         // 16

    dim3 grid((B + 3) / 4), block(128);
    lstm_warp_kernel<<<grid, block>>>(xin, Wih1, Whh1, bih1, bhh1,
                                      Wih2, Whh2, bih2, bhh2,
                                      (float*)d_out, B, T, F);
}